// round 16
// baseline (speedup 1.0000x reference)
#include <cuda_runtime.h>
#include <cuda_bf16.h>

// GRU via bf16 split-precision mma.sync, gate-major B, M=32 per warp.
// CTA = 64 threads (2 warps) / 64 seqs; warp w owns row-tiles w*16 and 32+w*16.
// B frags fused uint4 {bh0,bh1,bl0,bl1}; h_old recovered from kc2/3 A frags.

#define TT 24
#define NSEQ 65536
#define NT 64
#define RPU 36            // A row pitch in u32 (72 bf16 = 144 B)

#define OFF_AH 0          //  9216 B  Ahi [64][144B]
#define OFF_AL 9216       //  9216 B  Alo
#define OFF_BF 18432      // 24576 B  B frags: 48 chunks x 32 lanes x 16 B
#define OFF_BIAS 43008    //   512 B
#define OFF_WO 43520      //  2048 B
#define SMEM_BYTES 45568

typedef unsigned u32;

__device__ __forceinline__ float tanh_a(float x){
    float t; asm("tanh.approx.f32 %0,%1;" : "=f"(t) : "f"(x)); return t;
}
__device__ __forceinline__ float sigm_a(float x){
    return fmaf(0.5f, tanh_a(0.5f*x), 0.5f);
}
__device__ __forceinline__ void packhl(float a, float b, u32 &hi, u32 &lo){
    __nv_bfloat162 h2 = __floats2bfloat162_rn(a, b);
    __nv_bfloat162 l2 = __floats2bfloat162_rn(a - __bfloat162float(h2.x),
                                              b - __bfloat162float(h2.y));
    hi = *(u32*)&h2; lo = *(u32*)&l2;
}
__device__ __forceinline__ float wlook2(int k, int col,
        const float* __restrict__ Wih, const float* __restrict__ Whh){
    int g2 = col >> 5, u = col & 31;
    if (k < 32){ if (g2 == 3) return 0.f; return Wih[(g2*32+u)*32+k]; }
    if (g2 == 2) return 0.f;
    int row = (g2 == 3) ? (64+u) : (g2*32+u);
    return Whh[row*32 + (k-32)];
}

#define MMA(d,a0,a1,a2,a3,b0,b1) \
  asm volatile("mma.sync.aligned.m16n8k16.row.col.f32.bf16.bf16.f32 " \
    "{%0,%1,%2,%3},{%4,%5,%6,%7},{%8,%9},{%0,%1,%2,%3};" \
    : "+f"(d[0]),"+f"(d[1]),"+f"(d[2]),"+f"(d[3]) \
    : "r"(a0),"r"(a1),"r"(a2),"r"(a3),"r"(b0),"r"(b1))
#define G3(d, AH_, AL_, B_) { \
    MMA(d, AH_[0],AH_[1],AH_[2],AH_[3], B_.x, B_.y); \
    MMA(d, AL_[0],AL_[1],AL_[2],AL_[3], B_.x, B_.y); \
    MMA(d, AH_[0],AH_[1],AH_[2],AH_[3], B_.z, B_.w); }

#define ACT(Rv,Zv,Xv,Nv,Ho,B0,B1,B2,B3,OUT) { \
    float rr_=sigm_a((Rv)+(B0)), zz_=sigm_a((Zv)+(B1)); \
    float nn_=tanh_a((Xv)+(B2)+rr_*((Nv)+(B3))); \
    OUT = nn_ + zz_*((Ho)-nn_); }

#define PREF(tt) { size_t b_ = (size_t)(tt)*NSEQ + seqbase + tid; \
    const float4* q1 = (const float4*)(spat + b_*16); \
    pf[0]=q1[0]; pf[1]=q1[1]; pf[2]=q1[2]; pf[3]=q1[3]; \
    const float4* q2 = (const float4*)(met + b_*8); pf[4]=q2[0]; pf[5]=q2[1]; \
    const float4* q3 = (const float4*)(ctx + b_*8); pf[6]=q3[0]; pf[7]=q3[1]; }

#define XSTORE { _Pragma("unroll") \
    for (int q=0;q<4;q++){ int qe=(q+(tid>>3))&3; \
      float4 A_=pf[2*qe], B_=pf[2*qe+1]; u32 h_[4], l_[4]; \
      packhl(A_.x,A_.y,h_[0],l_[0]); packhl(A_.z,A_.w,h_[1],l_[1]); \
      packhl(B_.x,B_.y,h_[2],l_[2]); packhl(B_.z,B_.w,h_[3],l_[3]); \
      *(uint4*)(AHu + tid*RPU + qe*4) = *(uint4*)h_; \
      *(uint4*)(ALu + tid*RPU + qe*4) = *(uint4*)l_; } }

extern "C" __global__ void __launch_bounds__(NT, 5)
gru_tc(const float* __restrict__ spat, const float* __restrict__ met,
       const float* __restrict__ ctx,
       const float* __restrict__ W_ih, const float* __restrict__ W_hh,
       const float* __restrict__ b_ih, const float* __restrict__ b_hh,
       const float* __restrict__ Wo, float* __restrict__ out)
{
    extern __shared__ char sm[];
    u32* AHu = (u32*)(sm + OFF_AH);
    u32* ALu = (u32*)(sm + OFF_AL);
    const uint4* BF4 = (const uint4*)(sm + OFF_BF);
    float* sbias = (float*)(sm + OFF_BIAS);
    float* swo   = (float*)(sm + OFF_WO);

    const int tid = threadIdx.x;
    const int lane = tid & 31, wrp = tid >> 5;
    const int g = lane >> 2, tig = lane & 3;
    const int seqbase = blockIdx.x * 64;

    for (int i = tid; i < 4608; i += NT) ((u32*)sm)[i] = 0;   // zero A hi+lo

    // B fragments: chunk map [0,16) r j=0..3 | [16,32) z | [32,40) nx kc0-1 | [40,48) nh kc2-3
    for (int e = tid; e < 1536; e += NT){
        int chunk = e >> 5, ln = e & 31, j, kc;
        if (chunk < 16){ j = chunk>>2; kc = chunk&3; }
        else if (chunk < 32){ int c=chunk-16; j=4+(c>>2); kc=c&3; }
        else if (chunk < 40){ int c=chunk-32; j=8+(c>>1); kc=c&1; }
        else { int c=chunk-40; j=12+(c>>1); kc=2+(c&1); }
        int col = j*8 + (ln>>2);
        int k0 = kc*16 + 2*(ln&3);
        u32 bh0,bl0,bh1,bl1;
        packhl(wlook2(k0,col,W_ih,W_hh),   wlook2(k0+1,col,W_ih,W_hh), bh0, bl0);
        packhl(wlook2(k0+8,col,W_ih,W_hh), wlook2(k0+9,col,W_ih,W_hh), bh1, bl1);
        ((uint4*)(sm+OFF_BF))[e] = make_uint4(bh0,bh1,bl0,bl1);
    }
    if (tid < 32){
        sbias[tid]      = b_ih[tid]    + b_hh[tid];
        sbias[32 + tid] = b_ih[32+tid] + b_hh[32+tid];
        sbias[64 + tid] = b_ih[64+tid];
        sbias[96 + tid] = b_hh[64+tid];
    }
    for (int i = tid; i < 512; i += NT) swo[i] = Wo[i];

    float4 pf[8];
    PREF(0); XSTORE;
    __syncthreads();

    for (int t = 0; t < TT; t++){
        u32 ah[2][4][4], al[2][4][4];
        #pragma unroll
        for (int tl = 0; tl < 2; tl++){
            int rb = wrp*16 + tl*32, r0 = rb+g, r1 = r0+8;
            #pragma unroll
            for (int kc = 0; kc < 4; kc++){
                int c0 = kc*8 + tig;
                ah[tl][kc][0] = AHu[r0*RPU + c0];
                ah[tl][kc][1] = AHu[r1*RPU + c0];
                ah[tl][kc][2] = AHu[r0*RPU + c0 + 4];
                ah[tl][kc][3] = AHu[r1*RPU + c0 + 4];
                al[tl][kc][0] = ALu[r0*RPU + c0];
                al[tl][kc][1] = ALu[r1*RPU + c0];
                al[tl][kc][2] = ALu[r0*RPU + c0 + 4];
                al[tl][kc][3] = ALu[r1*RPU + c0 + 4];
            }
        }
        __syncthreads();                  // A reads done; writes may begin
        if (t + 1 < TT) PREF(t+1);

        #pragma unroll
        for (int ug = 0; ug < 4; ug++){
            float R[2][4]={{0}}, Z[2][4]={{0}}, X[2][4]={{0}}, N[2][4]={{0}};
            #pragma unroll
            for (int kc = 0; kc < 4; kc++){
                uint4 Br = BF4[(ug*4+kc)*32 + lane];
                G3(R[0], ah[0][kc], al[0][kc], Br);
                G3(R[1], ah[1][kc], al[1][kc], Br);
                uint4 Bz = BF4[(16+ug*4+kc)*32 + lane];
                G3(Z[0], ah[0][kc], al[0][kc], Bz);
                G3(Z[1], ah[1][kc], al[1][kc], Bz);
                if (kc < 2){
                    uint4 Bx = BF4[(32+ug*2+kc)*32 + lane];
                    G3(X[0], ah[0][kc], al[0][kc], Bx);
                    G3(X[1], ah[1][kc], al[1][kc], Bx);
                } else {
                    uint4 Bn = BF4[(40+ug*2+kc-2)*32 + lane];
                    G3(N[0], ah[0][kc], al[0][kc], Bn);
                    G3(N[1], ah[1][kc], al[1][kc], Bn);
                }
            }
            int u0 = ug*8 + 2*tig;
            float2 br = *(const float2*)(sbias+u0);
            float2 bz = *(const float2*)(sbias+32+u0);
            float2 bx = *(const float2*)(sbias+64+u0);
            float2 bn = *(const float2*)(sbias+96+u0);
            int hkc = 2 + (ug>>1), f0 = (ug&1)*2;
            #pragma unroll
            for (int tl = 0; tl < 2; tl++){
                int rb = wrp*16 + tl*32, r0 = rb+g, r1 = r0+8;
                __nv_bfloat162 H0 = *(__nv_bfloat162*)&ah[tl][hkc][f0];
                __nv_bfloat162 H1 = *(__nv_bfloat162*)&ah[tl][hkc][f0+1];
                __nv_bfloat162 L0 = *(__nv_bfloat162*)&al[tl][hkc][f0];
                __nv_bfloat162 L1 = *(__nv_bfloat162*)&al[tl][hkc][f0+1];
                float ho0 = __bfloat162float(H0.x)+__bfloat162float(L0.x);
                float ho1 = __bfloat162float(H0.y)+__bfloat162float(L0.y);
                float ho2 = __bfloat162float(H1.x)+__bfloat162float(L1.x);
                float ho3 = __bfloat162float(H1.y)+__bfloat162float(L1.y);
                float hn0,hn1,hn2,hn3;
                ACT(R[tl][0],Z[tl][0],X[tl][0],N[tl][0],ho0, br.x,bz.x,bx.x,bn.x, hn0);
                ACT(R[tl][1],Z[tl][1],X[tl][1],N[tl][1],ho1, br.y,bz.y,bx.y,bn.y, hn1);
                ACT(R[tl][2],Z[tl][2],X[tl][2],N[tl][2],ho2, br.x,bz.x,bx.x,bn.x, hn2);
                ACT(R[tl][3],Z[tl][3],X[tl][3],N[tl][3],ho3, br.y,bz.y,bx.y,bn.y, hn3);
                u32 hi_, lo_;
                int ci = 16 + ug*4 + tig;
                packhl(hn0,hn1,hi_,lo_); AHu[r0*RPU+ci]=hi_; ALu[r0*RPU+ci]=lo_;
                packhl(hn2,hn3,hi_,lo_); AHu[r1*RPU+ci]=hi_; ALu[r1*RPU+ci]=lo_;
            }
        }
        if (t + 1 < TT) XSTORE;
        __syncthreads();                  // A(t+1) complete
    }

    // final projection: h(64x32) @ Wo(32x16)
    {
        float h[32];
        #pragma unroll
        for (int c = 0; c < 16; c++){
            __nv_bfloat162 H = *(__nv_bfloat162*)&AHu[tid*RPU+16+c];
            __nv_bfloat162 L = *(__nv_bfloat162*)&ALu[tid*RPU+16+c];
            h[2*c]   = __bfloat162float(H.x)+__bfloat162float(L.x);
            h[2*c+1] = __bfloat162float(H.y)+__bfloat162float(L.y);
        }
        float o[16];
        #pragma unroll
        for (int j = 0; j < 16; j++) o[j] = 0.f;
        #pragma unroll 4
        for (int u = 0; u < 32; u++){
            float hv = h[u];
            #pragma unroll
            for (int j = 0; j < 16; j++) o[j] = fmaf(hv, swo[u*16+j], o[j]);
        }
        float4* op = (float4*)(out + (size_t)(seqbase + tid)*16);
        op[0] = make_float4(o[0],o[1],o[2],o[3]);
        op[1] = make_float4(o[4],o[5],o[6],o[7]);
        op[2] = make_float4(o[8],o[9],o[10],o[11]);
        op[3] = make_float4(o[12],o[13],o[14],o[15]);
    }
}

extern "C" void kernel_launch(void* const* d_in, const int* in_sizes, int n_in,
                              void* d_out, int out_size)
{
    const float* spat = (const float*)d_in[0];
    const float* met  = (const float*)d_in[1];
    const float* ctx  = (const float*)d_in[2];
    const float* W_ih = (const float*)d_in[3];
    const float* W_hh = (const float*)d_in[4];
    const float* b_ih = (const float*)d_in[5];
    const float* b_hh = (const float*)d_in[6];
    const float* Wo   = (const float*)d_in[7];
    float* out = (float*)d_out;

    cudaFuncSetAttribute(gru_tc, cudaFuncAttributeMaxDynamicSharedMemorySize, SMEM_BYTES);
    gru_tc<<<NSEQ/64, NT, SMEM_BYTES>>>(spat, met, ctx, W_ih, W_hh, b_ih, b_hh, Wo, out);
}

// round 17
// speedup vs baseline: 1.3380x; 1.3380x over previous
#include <cuda_runtime.h>
#include <cuda_bf16.h>

// GRU via bf16 split-precision mma.sync, gate-major B, M=16/warp, NT=128.
// CTA = 128 threads (4 warps) / 64 seqs; warp w owns rows [16w,16w+16).
// Fused uint4 B frags {bh0,bh1,bl0,bl1}; tanh.approx activations;
// h_old recovered from kc2/3 A fragments (no hreg array).

#define TT 24
#define NSEQ 65536
#define NT 128
#define RPU 36            // A row pitch in u32 (72 bf16 = 144 B)

#define OFF_AH 0          //  9216 B  Ahi [64][144B]
#define OFF_AL 9216       //  9216 B  Alo
#define OFF_BF 18432      // 24576 B  B frags: 48 chunks x 32 lanes x 16 B
#define OFF_BIAS 43008    //   512 B
#define OFF_WO 43520      //  2048 B
#define SMEM_BYTES 45568

typedef unsigned u32;

__device__ __forceinline__ float tanh_a(float x){
    float t; asm("tanh.approx.f32 %0,%1;" : "=f"(t) : "f"(x)); return t;
}
__device__ __forceinline__ float sigm_a(float x){
    return fmaf(0.5f, tanh_a(0.5f*x), 0.5f);
}
__device__ __forceinline__ void packhl(float a, float b, u32 &hi, u32 &lo){
    __nv_bfloat162 h2 = __floats2bfloat162_rn(a, b);
    __nv_bfloat162 l2 = __floats2bfloat162_rn(a - __bfloat162float(h2.x),
                                              b - __bfloat162float(h2.y));
    hi = *(u32*)&h2; lo = *(u32*)&l2;
}
__device__ __forceinline__ float wlook2(int k, int col,
        const float* __restrict__ Wih, const float* __restrict__ Whh){
    int g2 = col >> 5, u = col & 31;
    if (k < 32){ if (g2 == 3) return 0.f; return Wih[(g2*32+u)*32+k]; }
    if (g2 == 2) return 0.f;
    int row = (g2 == 3) ? (64+u) : (g2*32+u);
    return Whh[row*32 + (k-32)];
}

#define MMA(d,a0,a1,a2,a3,b0,b1) \
  asm volatile("mma.sync.aligned.m16n8k16.row.col.f32.bf16.bf16.f32 " \
    "{%0,%1,%2,%3},{%4,%5,%6,%7},{%8,%9},{%0,%1,%2,%3};" \
    : "+f"(d[0]),"+f"(d[1]),"+f"(d[2]),"+f"(d[3]) \
    : "r"(a0),"r"(a1),"r"(a2),"r"(a3),"r"(b0),"r"(b1))
#define G3(d, AH_, AL_, B_) { \
    MMA(d, AH_[0],AH_[1],AH_[2],AH_[3], B_.x, B_.y); \
    MMA(d, AL_[0],AL_[1],AL_[2],AL_[3], B_.x, B_.y); \
    MMA(d, AH_[0],AH_[1],AH_[2],AH_[3], B_.z, B_.w); }

#define ACT(Rv,Zv,Xv,Nv,Ho,B0,B1,B2,B3,OUT) { \
    float rr_=sigm_a((Rv)+(B0)), zz_=sigm_a((Zv)+(B1)); \
    float nn_=tanh_a((Xv)+(B2)+rr_*((Nv)+(B3))); \
    OUT = nn_ + zz_*((Ho)-nn_); }

#define PREF(tt) { size_t b_ = (size_t)(tt)*NSEQ + seqbase + s; \
    if (half == 0){ const float4* q1 = (const float4*)(spat + b_*16); \
      pf[0]=q1[0]; pf[1]=q1[1]; pf[2]=q1[2]; pf[3]=q1[3]; } \
    else { const float4* q2 = (const float4*)(met + b_*8); pf[0]=q2[0]; pf[1]=q2[1]; \
           const float4* q3 = (const float4*)(ctx + b_*8); pf[2]=q3[0]; pf[3]=q3[1]; } }

#define XSTORE { float c4[16]; \
    *(float4*)(c4+0)=pf[0]; *(float4*)(c4+4)=pf[1]; \
    *(float4*)(c4+8)=pf[2]; *(float4*)(c4+12)=pf[3]; \
    _Pragma("unroll") \
    for (int q=0;q<8;q++){ u32 h_,l_; \
      packhl(c4[2*q], c4[2*q+1], h_, l_); \
      AHu[s*RPU + kb + q] = h_; ALu[s*RPU + kb + q] = l_; } }

extern "C" __global__ void __launch_bounds__(NT, 5)
gru_tc(const float* __restrict__ spat, const float* __restrict__ met,
       const float* __restrict__ ctx,
       const float* __restrict__ W_ih, const float* __restrict__ W_hh,
       const float* __restrict__ b_ih, const float* __restrict__ b_hh,
       const float* __restrict__ Wo, float* __restrict__ out)
{
    extern __shared__ char sm[];
    u32* AHu = (u32*)(sm + OFF_AH);
    u32* ALu = (u32*)(sm + OFF_AL);
    const uint4* BF4 = (const uint4*)(sm + OFF_BF);
    float* sbias = (float*)(sm + OFF_BIAS);
    float* swo   = (float*)(sm + OFF_WO);

    const int tid = threadIdx.x;
    const int lane = tid & 31, wrp = tid >> 5;
    const int g = lane >> 2, tig = lane & 3;
    const int seqbase = blockIdx.x * 64;

    for (int i = tid; i < 4608; i += NT) ((u32*)sm)[i] = 0;   // zero A hi+lo

    // B fragments: chunk map [0,16) r | [16,32) z | [32,40) nx kc0-1 | [40,48) nh kc2-3
    for (int e = tid; e < 1536; e += NT){
        int chunk = e >> 5, ln = e & 31, j, kc;
        if (chunk < 16){ j = chunk>>2; kc = chunk&3; }
        else if (chunk < 32){ int c=chunk-16; j=4+(c>>2); kc=c&3; }
        else if (chunk < 40){ int c=chunk-32; j=8+(c>>1); kc=c&1; }
        else { int c=chunk-40; j=12+(c>>1); kc=2+(c&1); }
        int col = j*8 + (ln>>2);
        int k0 = kc*16 + 2*(ln&3);
        u32 bh0,bl0,bh1,bl1;
        packhl(wlook2(k0,col,W_ih,W_hh),   wlook2(k0+1,col,W_ih,W_hh), bh0, bl0);
        packhl(wlook2(k0+8,col,W_ih,W_hh), wlook2(k0+9,col,W_ih,W_hh), bh1, bl1);
        ((uint4*)(sm+OFF_BF))[e] = make_uint4(bh0,bh1,bl0,bl1);
    }
    if (tid < 32){
        sbias[tid]      = b_ih[tid]    + b_hh[tid];
        sbias[32 + tid] = b_ih[32+tid] + b_hh[32+tid];
        sbias[64 + tid] = b_ih[64+tid];
        sbias[96 + tid] = b_hh[64+tid];
    }
    for (int i = tid; i < 512; i += NT) swo[i] = Wo[i];

    const int s = tid >> 1, half = tid & 1, kb = half * 8;   // u32 col base
    float4 pf[4];
    PREF(0); XSTORE;
    __syncthreads();

    const int r0 = wrp*16 + g, r1 = r0 + 8;

    for (int t = 0; t < TT; t++){
        u32 ah[4][4], al[4][4];
        #pragma unroll
        for (int kc = 0; kc < 4; kc++){
            int c0 = kc*8 + tig;
            ah[kc][0] = AHu[r0*RPU + c0];
            ah[kc][1] = AHu[r1*RPU + c0];
            ah[kc][2] = AHu[r0*RPU + c0 + 4];
            ah[kc][3] = AHu[r1*RPU + c0 + 4];
            al[kc][0] = ALu[r0*RPU + c0];
            al[kc][1] = ALu[r1*RPU + c0];
            al[kc][2] = ALu[r0*RPU + c0 + 4];
            al[kc][3] = ALu[r1*RPU + c0 + 4];
        }
        __syncthreads();                  // A reads done; writes may begin
        if (t + 1 < TT) PREF(t+1);

        #pragma unroll
        for (int ug = 0; ug < 4; ug++){
            float R[4]={0,0,0,0}, Z[4]={0,0,0,0}, X[4]={0,0,0,0}, N[4]={0,0,0,0};
            #pragma unroll
            for (int kc = 0; kc < 4; kc++){
                uint4 Br = BF4[(ug*4+kc)*32 + lane];
                G3(R, ah[kc], al[kc], Br);
                uint4 Bz = BF4[(16+ug*4+kc)*32 + lane];
                G3(Z, ah[kc], al[kc], Bz);
                if (kc < 2){
                    uint4 Bx = BF4[(32+ug*2+kc)*32 + lane];
                    G3(X, ah[kc], al[kc], Bx);
                } else {
                    uint4 Bn = BF4[(40+ug*2+kc-2)*32 + lane];
                    G3(N, ah[kc], al[kc], Bn);
                }
            }
            int u0 = ug*8 + 2*tig;
            float2 br = *(const float2*)(sbias+u0);
            float2 bz = *(const float2*)(sbias+32+u0);
            float2 bx = *(const float2*)(sbias+64+u0);
            float2 bn = *(const float2*)(sbias+96+u0);
            int hkc = 2 + (ug>>1), f0 = (ug&1)*2;
            __nv_bfloat162 H0 = *(__nv_bfloat162*)&ah[hkc][f0];
            __nv_bfloat162 H1 = *(__nv_bfloat162*)&ah[hkc][f0+1];
            __nv_bfloat162 L0 = *(__nv_bfloat162*)&al[hkc][f0];
            __nv_bfloat162 L1 = *(__nv_bfloat162*)&al[hkc][f0+1];
            float ho0 = __bfloat162float(H0.x)+__bfloat162float(L0.x);
            float ho1 = __bfloat162float(H0.y)+__bfloat162float(L0.y);
            float ho2 = __bfloat162float(H1.x)+__bfloat162float(L1.x);
            float ho3 = __bfloat162float(H1.y)+__bfloat162float(L1.y);
            float hn0,hn1,hn2,hn3;
            ACT(R[0],Z[0],X[0],N[0],ho0, br.x,bz.x,bx.x,bn.x, hn0);
            ACT(R[1],Z[1],X[1],N[1],ho1, br.y,bz.y,bx.y,bn.y, hn1);
            ACT(R[2],Z[2],X[2],N[2],ho2, br.x,bz.x,bx.x,bn.x, hn2);
            ACT(R[3],Z[3],X[3],N[3],ho3, br.y,bz.y,bx.y,bn.y, hn3);
            u32 hi_, lo_;
            int ci = 16 + ug*4 + tig;
            packhl(hn0,hn1,hi_,lo_); AHu[r0*RPU+ci]=hi_; ALu[r0*RPU+ci]=lo_;
            packhl(hn2,hn3,hi_,lo_); AHu[r1*RPU+ci]=hi_; ALu[r1*RPU+ci]=lo_;
        }
        if (t + 1 < TT) XSTORE;
        __syncthreads();                  // A(t+1) complete
    }

    // final projection: h(64x32) @ Wo(32x16); 2 threads per seq
    {
        int ss = tid >> 1, jo = half * 8;
        float h[32];
        #pragma unroll
        for (int c = 0; c < 16; c++){
            __nv_bfloat162 H = *(__nv_bfloat162*)&AHu[ss*RPU+16+c];
            __nv_bfloat162 L = *(__nv_bfloat162*)&ALu[ss*RPU+16+c];
            h[2*c]   = __bfloat162float(H.x)+__bfloat162float(L.x);
            h[2*c+1] = __bfloat162float(H.y)+__bfloat162float(L.y);
        }
        float o[8];
        #pragma unroll
        for (int j = 0; j < 8; j++) o[j] = 0.f;
        #pragma unroll 8
        for (int u = 0; u < 32; u++){
            float hv = h[u];
            #pragma unroll
            for (int j = 0; j < 8; j++) o[j] = fmaf(hv, swo[u*16+jo+j], o[j]);
        }
        float* op = out + (size_t)(seqbase + ss)*16 + jo;
        *(float4*)(op)   = make_float4(o[0],o[1],o[2],o[3]);
        *(float4*)(op+4) = make_float4(o[4],o[5],o[6],o[7]);
    }
}

extern "C" void kernel_launch(void* const* d_in, const int* in_sizes, int n_in,
                              void* d_out, int out_size)
{
    const float* spat = (const float*)d_in[0];
    const float* met  = (const float*)d_in[1];
    const float* ctx  = (const float*)d_in[2];
    const float* W_ih = (const float*)d_in[3];
    const float* W_hh = (const float*)d_in[4];
    const float* b_ih = (const float*)d_in[5];
    const float* b_hh = (const float*)d_in[6];
    const float* Wo   = (const float*)d_in[7];
    float* out = (float*)d_out;

    cudaFuncSetAttribute(gru_tc, cudaFuncAttributeMaxDynamicSharedMemorySize, SMEM_BYTES);
    gru_tc<<<NSEQ/64, NT, SMEM_BYTES>>>(spat, met, ctx, W_ih, W_hh, b_ih, b_hh, Wo, out);
}